// round 12
// baseline (speedup 1.0000x reference)
#include <cuda_runtime.h>
#include <cuda_fp16.h>
#include <cstdint>

#define BATCH 8192
#define IN_OUT_DIM 1024
#define HALF 512
#define MID 4096

// Weight element offsets in the packed fp16 weight buffer (K-major, as input).
#define WO0 0                       // W0 [512,4096]
#define WO1 (WO0 + 512*4096)        // W1 [4096,4096]
#define WO2 (WO1 + 4096*4096)
#define WO3 (WO2 + 4096*4096)
#define WO4 (WO3 + 4096*4096)
#define WO5 (WO4 + 4096*4096)       // W5 [4096,512]
#define WTOT (WO5 + 4096*512)

// ---------------------------------------------------------------------------
// Scratch (allocation-free rule -> device globals)
// ---------------------------------------------------------------------------
__device__ __align__(1024) unsigned short g_odd[BATCH * HALF];        // fp16
__device__ __align__(1024) unsigned short g_a[2][BATCH * MID];        // fp16
__device__ __align__(1024) unsigned short g_w[WTOT];                  // fp16
__device__ __align__(1024) float g_m[BATCH * HALF];

// ---------------------------------------------------------------------------
// PTX helpers (sm_80-level: cp.async, ldmatrix, mma.sync)
// ---------------------------------------------------------------------------
__device__ __forceinline__ uint32_t smem_to_u32(const void* p) {
    uint32_t a;
    asm("{ .reg .u64 t; cvta.to.shared.u64 t, %1; cvt.u32.u64 %0, t; }" : "=r"(a) : "l"(p));
    return a;
}

__device__ __forceinline__ void cp_async16(uint32_t dst, const void* src) {
    asm volatile("cp.async.cg.shared.global [%0], [%1], 16;" :: "r"(dst), "l"(src));
}
__device__ __forceinline__ void cp_commit() {
    asm volatile("cp.async.commit_group;" ::: "memory");
}
template <int N>
__device__ __forceinline__ void cp_wait() {
    asm volatile("cp.async.wait_group %0;" :: "n"(N) : "memory");
}

#define LDMATRIX_X4(r0, r1, r2, r3, addr) \
    asm volatile("ldmatrix.sync.aligned.m8n8.x4.shared.b16 {%0,%1,%2,%3}, [%4];" \
                 : "=r"(r0), "=r"(r1), "=r"(r2), "=r"(r3) : "r"(addr))

#define LDMATRIX_X4_TRANS(r0, r1, r2, r3, addr) \
    asm volatile("ldmatrix.sync.aligned.m8n8.x4.trans.shared.b16 {%0,%1,%2,%3}, [%4];" \
                 : "=r"(r0), "=r"(r1), "=r"(r2), "=r"(r3) : "r"(addr))

// D(f32) += A(f16,row) * B(f16,col);  C/D 4 regs, A 4 regs, B 2 regs
__device__ __forceinline__ void mma_f16(float* c, const uint32_t* a, const uint32_t* b) {
    asm volatile(
        "mma.sync.aligned.m16n8k16.row.col.f32.f16.f16.f32 "
        "{%0,%1,%2,%3}, {%4,%5,%6,%7}, {%8,%9}, {%0,%1,%2,%3};"
        : "+f"(c[0]), "+f"(c[1]), "+f"(c[2]), "+f"(c[3])
        : "r"(a[0]), "r"(a[1]), "r"(a[2]), "r"(a[3]), "r"(b[0]), "r"(b[1]));
}

// ---------------------------------------------------------------------------
// Prep kernels
// ---------------------------------------------------------------------------
__global__ void extract_odd_f16(const float* __restrict__ x,
                                unsigned short* __restrict__ o) {
    int i = blockIdx.x * blockDim.x + threadIdx.x;
    if (i < BATCH * HALF) {
        float2 v = reinterpret_cast<const float2*>(x)[i];
        o[i] = __half_as_ushort(__float2half_rn(v.y));
    }
}

// Streaming fp32 -> fp16 convert (no transpose; layout preserved [K,N]).
__global__ void convert_f16(const float* __restrict__ W,
                            unsigned short* __restrict__ T, int n4) {
    int i = blockIdx.x * blockDim.x + threadIdx.x;
    if (i < n4) {
        float4 v = reinterpret_cast<const float4*>(W)[i];
        uint32_t lo = (uint32_t)__half_as_ushort(__float2half_rn(v.x)) |
                      ((uint32_t)__half_as_ushort(__float2half_rn(v.y)) << 16);
        uint32_t hi = (uint32_t)__half_as_ushort(__float2half_rn(v.z)) |
                      ((uint32_t)__half_as_ushort(__float2half_rn(v.w)) << 16);
        reinterpret_cast<uint2*>(T)[i] = make_uint2(lo, hi);
    }
}

// ---------------------------------------------------------------------------
// fp16 HMMA GEMM: C[M,N] = A[M,K] @ W[K,N] + bias, fp32 accum.
// A row-major (K-fast); W K-major [K,N] loaded with ldmatrix.trans.
// BM=128, BN=128, BK=64; 256 threads (8 warps, 2x4 of 64x32 warp tiles);
// 3-stage cp.async pipeline, ONE __syncthreads per iteration; occupancy 2.
// ---------------------------------------------------------------------------
#define BM 128
#define BN 128
#define BK 64
#define NTHREADS 256
#define NSTAGE 3
#define A_OFF 0
#define B_OFF 16384
#define STAGE_SZ 32768
#define SMEM_TOTAL (NSTAGE * STAGE_SZ + 1024)

// A tile: 128 rows x 128B (64 fp16): sw = (row*128 + col) ^ ((row&7)<<4)
__device__ __forceinline__ uint32_t swzA(int row, int bytecol) {
    return (uint32_t)(row * 128 + bytecol) ^ (uint32_t)((row & 7) << 4);
}
// B tile: 64 k-rows x 256B (128 fp16): same XOR pattern (256B row stride is
// bank-invariant, XOR spreads 8 consecutive rows over 8 distinct 16B groups)
__device__ __forceinline__ uint32_t swzB(int row, int bytecol) {
    return (uint32_t)(row * 256 + bytecol) ^ (uint32_t)((row & 7) << 4);
}

__device__ __forceinline__ void load_stage(
    uint32_t stage_base,
    const unsigned short* A, int lda,
    const unsigned short* B, int ldb,
    int tid) {
    #pragma unroll
    for (int j = 0; j < 4; j++) {
        int c = tid + NTHREADS * j;
        // A: 128 rows x 8 chunks of 16B
        int arow = c >> 3;
        int acol = (c & 7) * 16;
        cp_async16(stage_base + A_OFF + swzA(arow, acol),
                   (const char*)(A + (size_t)arow * lda) + acol);
        // B: 64 k-rows x 16 chunks of 16B
        int brow = c >> 4;
        int bcol = (c & 15) * 16;
        cp_async16(stage_base + B_OFF + swzB(brow, bcol),
                   (const char*)(B + (size_t)brow * ldb) + bcol);
    }
}

template <bool RELU, bool FINAL>
__global__ void __launch_bounds__(NTHREADS, 2)
mma_gemm(const unsigned short* __restrict__ A,
         const unsigned short* __restrict__ B,   // [K,N] fp16, K-major
         const float* __restrict__ bias,
         unsigned short* __restrict__ C,     // fp16 activation out
         float* __restrict__ Cf,             // fp32 out (FINAL)
         int N, int K) {
    extern __shared__ char dyn_smem[];
    const uint32_t sbase = (smem_to_u32(dyn_smem) + 1023u) & ~1023u;

    const int tid = threadIdx.x;
    const int wid = tid >> 5;
    const int lane = tid & 31;
    const int warp_m = wid & 1;   // 2 warps over M (64 rows each)
    const int warp_n = wid >> 1;  // 4 warps over N (32 cols each)

    const int m0 = blockIdx.y * BM;
    const int n0 = blockIdx.x * BN;
    const unsigned short* At = A + (size_t)m0 * K;
    const unsigned short* Bt = B + n0;   // column offset; rows advance with k

    const int niter = K / BK;

    // Prologue: fill NSTAGE-1 stages
    #pragma unroll
    for (int s = 0; s < NSTAGE - 1; s++) {
        load_stage(sbase + s * STAGE_SZ,
                   At + s * BK, K,
                   Bt + (size_t)(s * BK) * N, N, tid);
        cp_commit();
    }

    float acc[4][4][4];
    #pragma unroll
    for (int mi = 0; mi < 4; mi++)
        #pragma unroll
        for (int nj = 0; nj < 4; nj++)
            #pragma unroll
            for (int q = 0; q < 4; q++) acc[mi][nj][q] = 0.0f;

    // Per-thread ldmatrix address components
    const int a_row_base = warp_m * 64 + (lane & 15);   // + mi*16
    const int a_col_sel = ((lane >> 4) & 1) * 16;       // + kk*32
    // B (trans): lanes 0-15 supply k-rows 0..15, lanes 16-31 same rows at n+8
    const int b_kr = lane & 15;                         // + kk*16
    const int b_nc = (lane >> 4) * 8;                   // + warp_n*32 + njp*16

    for (int i = 0; i < niter; i++) {
        cp_wait<NSTAGE - 2>();   // stage i resident
        __syncthreads();         // all warps past compute(i-1); its slot is free

        if (i + NSTAGE - 1 < niter) {
            int kb = (i + NSTAGE - 1) * BK;
            load_stage(sbase + ((i + NSTAGE - 1) % NSTAGE) * STAGE_SZ,
                       At + kb, K,
                       Bt + (size_t)kb * N, N, tid);
        }
        cp_commit();  // uniform group accounting (possibly empty)

        const uint32_t so = sbase + (i % NSTAGE) * STAGE_SZ;

        #pragma unroll
        for (int kk = 0; kk < 4; kk++) {
            uint32_t a_r[4][4];
            const int acol = a_col_sel + kk * 32;
            #pragma unroll
            for (int mi = 0; mi < 4; mi++) {
                const int row = a_row_base + mi * 16;
                const uint32_t sw = swzA(row, acol);
                LDMATRIX_X4(a_r[mi][0], a_r[mi][1], a_r[mi][2], a_r[mi][3],
                            so + A_OFF + sw);
            }
            const int brow = kk * 16 + b_kr;
            #pragma unroll
            for (int njp = 0; njp < 2; njp++) {
                uint32_t b_r[2][2];
                const int bcolb = (warp_n * 32 + njp * 16 + b_nc) * 2;
                const uint32_t sw = swzB(brow, bcolb);
                // tiles: (k0..7,n0..7)->b0, (k8..15,n0..7)->b1, then n+8 pair
                LDMATRIX_X4_TRANS(b_r[0][0], b_r[0][1], b_r[1][0], b_r[1][1],
                                  so + B_OFF + sw);
                #pragma unroll
                for (int mi = 0; mi < 4; mi++) {
                    #pragma unroll
                    for (int njq = 0; njq < 2; njq++) {
                        mma_f16(acc[mi][2 * njp + njq], a_r[mi], b_r[njq]);
                    }
                }
            }
        }
    }

    // Epilogue: c0,c1 -> row g, cols p,p+1; c2,c3 -> row g+8
    const int g = lane >> 2;
    const int p = (lane & 3) * 2;
    #pragma unroll
    for (int mi = 0; mi < 4; mi++) {
        #pragma unroll
        for (int nj = 0; nj < 4; nj++) {
            const int col = n0 + warp_n * 32 + nj * 8 + p;
            const float bx = bias[col];
            const float by = bias[col + 1];
            #pragma unroll
            for (int half = 0; half < 2; half++) {
                const int r = m0 + warp_m * 64 + mi * 16 + g + half * 8;
                float v0 = acc[mi][nj][2 * half + 0] + bx;
                float v1 = acc[mi][nj][2 * half + 1] + by;
                if (RELU) {
                    v0 = fmaxf(v0, 0.0f);
                    v1 = fmaxf(v1, 0.0f);
                }
                if (FINAL) {
                    float2 o = make_float2(v0, v1);
                    *reinterpret_cast<float2*>(Cf + (size_t)r * N + col) = o;
                } else {
                    uint32_t h0 = (uint32_t)__half_as_ushort(__float2half_rn(v0));
                    uint32_t h1 = (uint32_t)__half_as_ushort(__float2half_rn(v1));
                    *reinterpret_cast<uint32_t*>(C + (size_t)r * N + col) =
                        (h1 << 16) | h0;
                }
            }
        }
    }
}

// ---------------------------------------------------------------------------
// Finalize: out[b,2k] = x[b,2k] + m[b,k]; out[b,2k+1] = x[b,2k+1]; ldj tail.
// ---------------------------------------------------------------------------
__global__ void finalize_kernel(const float* __restrict__ x,
                                const float* __restrict__ m,
                                const float* __restrict__ ldj,
                                float* __restrict__ out,
                                int tail) {
    int i = blockIdx.x * blockDim.x + threadIdx.x;
    if (i < BATCH * HALF) {
        float2 v = reinterpret_cast<const float2*>(x)[i];
        float2 o;
        o.x = v.x + m[i];
        o.y = v.y;
        reinterpret_cast<float2*>(out)[i] = o;
    }
    if (i < tail) {
        out[BATCH * IN_OUT_DIM + i] = ldj[i];
    }
}

// ---------------------------------------------------------------------------
extern "C" void kernel_launch(void* const* d_in, const int* in_sizes, int n_in,
                              void* d_out, int out_size) {
    const float* x   = (const float*)d_in[0];
    const float* ldj = (const float*)d_in[1];
    const float* W[6] = {(const float*)d_in[2], (const float*)d_in[4],
                         (const float*)d_in[6], (const float*)d_in[8],
                         (const float*)d_in[10], (const float*)d_in[12]};
    const float* b[6] = {(const float*)d_in[3], (const float*)d_in[5],
                         (const float*)d_in[7], (const float*)d_in[9],
                         (const float*)d_in[11], (const float*)d_in[13]};
    float* out = (float*)d_out;

    unsigned short *odd, *a, *w;
    float* m;
    cudaGetSymbolAddress((void**)&odd, g_odd);
    cudaGetSymbolAddress((void**)&a, g_a);
    cudaGetSymbolAddress((void**)&w, g_w);
    cudaGetSymbolAddress((void**)&m, g_m);

    unsigned short* ab[2] = {a, a + (size_t)BATCH * MID};
    const size_t woff[6] = {WO0, WO1, WO2, WO3, WO4, WO5};
    const int wsize[6] = {512 * 4096, 4096 * 4096, 4096 * 4096,
                          4096 * 4096, 4096 * 4096, 4096 * 512};

    // --- prep ---
    const int n_pairs = BATCH * HALF;
    extract_odd_f16<<<(n_pairs + 255) / 256, 256>>>(x, odd);
    for (int i = 0; i < 6; i++) {
        int n4 = wsize[i] / 4;
        convert_f16<<<(n4 + 255) / 256, 256>>>(W[i], w + woff[i], n4);
    }

    // --- GEMM chain ---
    cudaFuncSetAttribute(mma_gemm<true, false>,
                         cudaFuncAttributeMaxDynamicSharedMemorySize, SMEM_TOTAL);
    cudaFuncSetAttribute(mma_gemm<false, true>,
                         cudaFuncAttributeMaxDynamicSharedMemorySize, SMEM_TOTAL);

    dim3 blk(NTHREADS);
    dim3 grid_mid(MID / BN, BATCH / BM);   // (32, 64)
    dim3 grid_last(HALF / BN, BATCH / BM); // (4, 64)

    // L0: [8192,512] @ W0[512,4096] -> [8192,4096], relu
    mma_gemm<true, false><<<grid_mid, blk, SMEM_TOTAL>>>(
        odd, w + woff[0], b[0], ab[0], nullptr, MID, HALF);
    // L1..L4: [8192,4096] @ W[4096,4096] -> [8192,4096], relu (ping-pong)
    mma_gemm<true, false><<<grid_mid, blk, SMEM_TOTAL>>>(
        ab[0], w + woff[1], b[1], ab[1], nullptr, MID, MID);
    mma_gemm<true, false><<<grid_mid, blk, SMEM_TOTAL>>>(
        ab[1], w + woff[2], b[2], ab[0], nullptr, MID, MID);
    mma_gemm<true, false><<<grid_mid, blk, SMEM_TOTAL>>>(
        ab[0], w + woff[3], b[3], ab[1], nullptr, MID, MID);
    mma_gemm<true, false><<<grid_mid, blk, SMEM_TOTAL>>>(
        ab[1], w + woff[4], b[4], ab[0], nullptr, MID, MID);
    // L5: [8192,4096] @ W5[4096,512] -> [8192,512] fp32, no relu
    mma_gemm<false, true><<<grid_last, blk, SMEM_TOTAL>>>(
        ab[0], w + woff[5], b[5], nullptr, m, HALF, MID);

    int tail = out_size - BATCH * IN_OUT_DIM;
    if (tail < 0) tail = 0;
    finalize_kernel<<<(n_pairs + 255) / 256, 256>>>(x, m, ldj, out, tail);
}

// round 13
// speedup vs baseline: 1.0378x; 1.0378x over previous
#include <cuda_runtime.h>
#include <cuda_fp16.h>
#include <cstdint>

#define BATCH 8192
#define IN_OUT_DIM 1024
#define HALF 512
#define MID 4096

// Weight element offsets in the packed transposed-weight buffer ([N,K] fp16).
#define WO0 0                       // Wt0 [4096,512]
#define WO1 (WO0 + 4096*512)        // Wt1 [4096,4096]
#define WO2 (WO1 + 4096*4096)
#define WO3 (WO2 + 4096*4096)
#define WO4 (WO3 + 4096*4096)
#define WO5 (WO4 + 4096*4096)       // Wt5 [512,4096]
#define WTOT (WO5 + 512*4096)

// ---------------------------------------------------------------------------
// Scratch (allocation-free rule -> device globals)
// ---------------------------------------------------------------------------
__device__ __align__(1024) unsigned short g_odd[BATCH * HALF];        // fp16
__device__ __align__(1024) unsigned short g_a[2][BATCH * MID];        // fp16
__device__ __align__(1024) unsigned short g_w[WTOT];                  // fp16
__device__ __align__(1024) float g_m[BATCH * HALF];

// ---------------------------------------------------------------------------
// PTX helpers (sm_80-level: cp.async, ldmatrix, mma.sync)
// ---------------------------------------------------------------------------
__device__ __forceinline__ uint32_t smem_to_u32(const void* p) {
    uint32_t a;
    asm("{ .reg .u64 t; cvta.to.shared.u64 t, %1; cvt.u32.u64 %0, t; }" : "=r"(a) : "l"(p));
    return a;
}

__device__ __forceinline__ void cp_async16(uint32_t dst, const void* src) {
    asm volatile("cp.async.cg.shared.global [%0], [%1], 16;" :: "r"(dst), "l"(src));
}
__device__ __forceinline__ void cp_commit() {
    asm volatile("cp.async.commit_group;" ::: "memory");
}
template <int N>
__device__ __forceinline__ void cp_wait() {
    asm volatile("cp.async.wait_group %0;" :: "n"(N) : "memory");
}

#define LDMATRIX_X4(r0, r1, r2, r3, addr) \
    asm volatile("ldmatrix.sync.aligned.m8n8.x4.shared.b16 {%0,%1,%2,%3}, [%4];" \
                 : "=r"(r0), "=r"(r1), "=r"(r2), "=r"(r3) : "r"(addr))

// D(f32) += A(f16,row) * B(f16,col);  C/D 4 regs, A 4 regs, B 2 regs
__device__ __forceinline__ void mma_f16(float* c, const uint32_t* a, const uint32_t* b) {
    asm volatile(
        "mma.sync.aligned.m16n8k16.row.col.f32.f16.f16.f32 "
        "{%0,%1,%2,%3}, {%4,%5,%6,%7}, {%8,%9}, {%0,%1,%2,%3};"
        : "+f"(c[0]), "+f"(c[1]), "+f"(c[2]), "+f"(c[3])
        : "r"(a[0]), "r"(a[1]), "r"(a[2]), "r"(a[3]), "r"(b[0]), "r"(b[1]));
}

// ---------------------------------------------------------------------------
// Prep kernels
// ---------------------------------------------------------------------------
__global__ void extract_odd_f16(const float* __restrict__ x,
                                unsigned short* __restrict__ o) {
    int i = blockIdx.x * blockDim.x + threadIdx.x;
    if (i < BATCH * HALF) {
        float2 v = reinterpret_cast<const float2*>(x)[i];
        o[i] = __half_as_ushort(__float2half_rn(v.y));
    }
}

// W [K,N] fp32 (row-major) -> Wt [N,K] fp16.  64x64 tile, 256 threads.
// Loads: float4 coalesced (256B/row). Stores: uint4; 8 lanes cover one
// n-row's 8 chunks -> 4 x 128B transactions per warp store.
__global__ void transpose_f16(const float* __restrict__ W,
                              unsigned short* __restrict__ T,
                              int K, int N) {
    __shared__ float t[64][65];
    const int n0 = blockIdx.x * 64, k0 = blockIdx.y * 64;
    const int tid = threadIdx.x;

    // Phase 1: load 64 k-rows x 64 n-cols (1024 float4, 4 per thread)
    #pragma unroll
    for (int j = 0; j < 4; j++) {
        int idx = tid + 256 * j;
        int r = idx >> 4;            // k-row 0..63
        int c4 = (idx & 15) * 4;     // n-col group
        float4 v = *reinterpret_cast<const float4*>(
            W + (size_t)(k0 + r) * N + n0 + c4);
        t[r][c4 + 0] = v.x;
        t[r][c4 + 1] = v.y;
        t[r][c4 + 2] = v.z;
        t[r][c4 + 3] = v.w;
    }
    __syncthreads();

    // Phase 2: write 64 n-rows x 64 k (8 uint4 chunks per n-row)
    const int lane = tid & 31;
    const int w = tid >> 5;
    const int chunk = lane & 7;          // k-chunk 0..7 (8 fp16 each)
    #pragma unroll
    for (int rep = 0; rep < 2; rep++) {
        int nloc = w * 8 + rep * 4 + (lane >> 3);  // n-row 0..63
        unsigned short h[8];
        #pragma unroll
        for (int j = 0; j < 8; j++)
            h[j] = __half_as_ushort(__float2half_rn(t[chunk * 8 + j][nloc]));
        uint4 o;
        o.x = (uint32_t)h[0] | ((uint32_t)h[1] << 16);
        o.y = (uint32_t)h[2] | ((uint32_t)h[3] << 16);
        o.z = (uint32_t)h[4] | ((uint32_t)h[5] << 16);
        o.w = (uint32_t)h[6] | ((uint32_t)h[7] << 16);
        *reinterpret_cast<uint4*>(T + (size_t)(n0 + nloc) * K + k0 + chunk * 8) = o;
    }
}

// ---------------------------------------------------------------------------
// fp16 HMMA GEMM: C[M,N] = A[M,K] @ Wt[N,K]^T + bias, fp32 accum.
// BM=128, BN=128, BK=64; 256 threads (8 warps, 2x4 of 64x32 warp tiles);
// 3-stage cp.async pipeline, ONE __syncthreads per iteration; occupancy 2.
// ---------------------------------------------------------------------------
#define BM 128
#define BN 128
#define BK 64
#define NTHREADS 256
#define NSTAGE 3
#define A_OFF 0
#define B_OFF 16384
#define STAGE_SZ 32768
#define SMEM_TOTAL (NSTAGE * STAGE_SZ + 1024)

// 128B rows (64 fp16): sw = (row*128 + col) ^ ((row&7)<<4)
__device__ __forceinline__ uint32_t swz(int row, int bytecol) {
    return (uint32_t)(row * 128 + bytecol) ^ (uint32_t)((row & 7) << 4);
}

__device__ __forceinline__ void load_stage(
    uint32_t stage_base,
    const unsigned short* A, const unsigned short* B,
    int lda, int tid) {
    // Each operand tile: 128 rows x 128B = 1024 chunks of 16B -> 4 per thread
    #pragma unroll
    for (int j = 0; j < 4; j++) {
        int c = tid + NTHREADS * j;
        int row = c >> 3;
        int col = (c & 7) * 16;
        uint32_t sw = swz(row, col);
        cp_async16(stage_base + A_OFF + sw, (const char*)(A + (size_t)row * lda) + col);
        cp_async16(stage_base + B_OFF + sw, (const char*)(B + (size_t)row * lda) + col);
    }
}

template <bool RELU, bool FINAL>
__global__ void __launch_bounds__(NTHREADS, 2)
mma_gemm(const unsigned short* __restrict__ A,
         const unsigned short* __restrict__ B,
         const float* __restrict__ bias,
         unsigned short* __restrict__ C,     // fp16 activation out
         float* __restrict__ Cf,             // fp32 out (FINAL)
         int N, int K) {
    extern __shared__ char dyn_smem[];
    const uint32_t sbase = (smem_to_u32(dyn_smem) + 1023u) & ~1023u;

    const int tid = threadIdx.x;
    const int wid = tid >> 5;
    const int lane = tid & 31;
    const int warp_m = wid & 1;   // 2 warps over M (64 rows each)
    const int warp_n = wid >> 1;  // 4 warps over N (32 cols each)

    const int m0 = blockIdx.y * BM;
    const int n0 = blockIdx.x * BN;
    const unsigned short* At = A + (size_t)m0 * K;
    const unsigned short* Bt = B + (size_t)n0 * K;

    const int niter = K / BK;

    // Prologue: fill NSTAGE-1 stages
    #pragma unroll
    for (int s = 0; s < NSTAGE - 1; s++) {
        load_stage(sbase + s * STAGE_SZ, At + s * BK, Bt + s * BK, K, tid);
        cp_commit();
    }

    float acc[4][4][4];
    #pragma unroll
    for (int mi = 0; mi < 4; mi++)
        #pragma unroll
        for (int nj = 0; nj < 4; nj++)
            #pragma unroll
            for (int q = 0; q < 4; q++) acc[mi][nj][q] = 0.0f;

    // Per-thread ldmatrix address components
    const int a_row_base = warp_m * 64 + (lane & 15);                // + mi*16
    const int a_col_sel = ((lane >> 4) & 1) * 16;                    // + kk*32
    const int b_row_base = warp_n * 32 + (lane & 7) + ((lane >> 4) & 1) * 8;  // + njp*16
    const int b_col_sel = ((lane >> 3) & 1) * 16;                    // + kk*32

    for (int i = 0; i < niter; i++) {
        cp_wait<NSTAGE - 2>();   // stage i resident
        __syncthreads();         // all warps past compute(i-1); its slot is free

        if (i + NSTAGE - 1 < niter) {
            int kb = (i + NSTAGE - 1) * BK;
            load_stage(sbase + ((i + NSTAGE - 1) % NSTAGE) * STAGE_SZ,
                       At + kb, Bt + kb, K, tid);
        }
        cp_commit();  // uniform group accounting (possibly empty)

        const uint32_t so = sbase + (i % NSTAGE) * STAGE_SZ;

        #pragma unroll
        for (int kk = 0; kk < 4; kk++) {
            uint32_t a_r[4][4];
            const int acol = a_col_sel + kk * 32;
            const int bcol = b_col_sel + kk * 32;
            #pragma unroll
            for (int mi = 0; mi < 4; mi++) {
                const int row = a_row_base + mi * 16;
                const uint32_t sw = swz(row, acol);
                LDMATRIX_X4(a_r[mi][0], a_r[mi][1], a_r[mi][2], a_r[mi][3],
                            so + A_OFF + sw);
            }
            #pragma unroll
            for (int njp = 0; njp < 2; njp++) {
                uint32_t b_r[2][2];
                const int row = b_row_base + njp * 16;
                const uint32_t sw = swz(row, bcol);
                LDMATRIX_X4(b_r[0][0], b_r[0][1], b_r[1][0], b_r[1][1],
                            so + B_OFF + sw);
                #pragma unroll
                for (int mi = 0; mi < 4; mi++) {
                    #pragma unroll
                    for (int njq = 0; njq < 2; njq++) {
                        mma_f16(acc[mi][2 * njp + njq], a_r[mi], b_r[njq]);
                    }
                }
            }
        }
    }

    // Epilogue: c0,c1 -> row g, cols p,p+1; c2,c3 -> row g+8
    const int g = lane >> 2;
    const int p = (lane & 3) * 2;
    #pragma unroll
    for (int mi = 0; mi < 4; mi++) {
        #pragma unroll
        for (int nj = 0; nj < 4; nj++) {
            const int col = n0 + warp_n * 32 + nj * 8 + p;
            const float bx = bias[col];
            const float by = bias[col + 1];
            #pragma unroll
            for (int half = 0; half < 2; half++) {
                const int r = m0 + warp_m * 64 + mi * 16 + g + half * 8;
                float v0 = acc[mi][nj][2 * half + 0] + bx;
                float v1 = acc[mi][nj][2 * half + 1] + by;
                if (RELU) {
                    v0 = fmaxf(v0, 0.0f);
                    v1 = fmaxf(v1, 0.0f);
                }
                if (FINAL) {
                    float2 o = make_float2(v0, v1);
                    *reinterpret_cast<float2*>(Cf + (size_t)r * N + col) = o;
                } else {
                    uint32_t h0 = (uint32_t)__half_as_ushort(__float2half_rn(v0));
                    uint32_t h1 = (uint32_t)__half_as_ushort(__float2half_rn(v1));
                    *reinterpret_cast<uint32_t*>(C + (size_t)r * N + col) =
                        (h1 << 16) | h0;
                }
            }
        }
    }
}

// ---------------------------------------------------------------------------
// Finalize: out[b,2k] = x[b,2k] + m[b,k]; out[b,2k+1] = x[b,2k+1]; ldj tail.
// ---------------------------------------------------------------------------
__global__ void finalize_kernel(const float* __restrict__ x,
                                const float* __restrict__ m,
                                const float* __restrict__ ldj,
                                float* __restrict__ out,
                                int tail) {
    int i = blockIdx.x * blockDim.x + threadIdx.x;
    if (i < BATCH * HALF) {
        float2 v = reinterpret_cast<const float2*>(x)[i];
        float2 o;
        o.x = v.x + m[i];
        o.y = v.y;
        reinterpret_cast<float2*>(out)[i] = o;
    }
    if (i < tail) {
        out[BATCH * IN_OUT_DIM + i] = ldj[i];
    }
}

// ---------------------------------------------------------------------------
extern "C" void kernel_launch(void* const* d_in, const int* in_sizes, int n_in,
                              void* d_out, int out_size) {
    const float* x   = (const float*)d_in[0];
    const float* ldj = (const float*)d_in[1];
    const float* W[6] = {(const float*)d_in[2], (const float*)d_in[4],
                         (const float*)d_in[6], (const float*)d_in[8],
                         (const float*)d_in[10], (const float*)d_in[12]};
    const float* b[6] = {(const float*)d_in[3], (const float*)d_in[5],
                         (const float*)d_in[7], (const float*)d_in[9],
                         (const float*)d_in[11], (const float*)d_in[13]};
    float* out = (float*)d_out;

    unsigned short *odd, *a, *w;
    float* m;
    cudaGetSymbolAddress((void**)&odd, g_odd);
    cudaGetSymbolAddress((void**)&a, g_a);
    cudaGetSymbolAddress((void**)&w, g_w);
    cudaGetSymbolAddress((void**)&m, g_m);

    unsigned short* ab[2] = {a, a + (size_t)BATCH * MID};
    const size_t woff[6] = {WO0, WO1, WO2, WO3, WO4, WO5};

    // --- prep ---
    const int n_pairs = BATCH * HALF;
    extract_odd_f16<<<(n_pairs + 255) / 256, 256>>>(x, odd);

    // W0 [512,4096] -> Wt0 [4096,512]
    transpose_f16<<<dim3(4096 / 64, 512 / 64), 256>>>(W[0], w + woff[0], 512, 4096);
    for (int i = 1; i <= 4; i++)
        transpose_f16<<<dim3(4096 / 64, 4096 / 64), 256>>>(W[i], w + woff[i], 4096, 4096);
    // W5 [4096,512] -> Wt5 [512,4096]
    transpose_f16<<<dim3(512 / 64, 4096 / 64), 256>>>(W[5], w + woff[5], 4096, 512);

    // --- GEMM chain ---
    cudaFuncSetAttribute(mma_gemm<true, false>,
                         cudaFuncAttributeMaxDynamicSharedMemorySize, SMEM_TOTAL);
    cudaFuncSetAttribute(mma_gemm<false, true>,
                         cudaFuncAttributeMaxDynamicSharedMemorySize, SMEM_TOTAL);

    dim3 blk(NTHREADS);
    dim3 grid_mid(MID / BN, BATCH / BM);   // (32, 64)
    dim3 grid_last(HALF / BN, BATCH / BM); // (4, 64)

    // L0: [8192,512] @ Wt0^T -> [8192,4096], relu
    mma_gemm<true, false><<<grid_mid, blk, SMEM_TOTAL>>>(
        odd, w + woff[0], b[0], ab[0], nullptr, MID, HALF);
    // L1..L4: [8192,4096] @ Wt^T -> [8192,4096], relu (ping-pong)
    mma_gemm<true, false><<<grid_mid, blk, SMEM_TOTAL>>>(
        ab[0], w + woff[1], b[1], ab[1], nullptr, MID, MID);
    mma_gemm<true, false><<<grid_mid, blk, SMEM_TOTAL>>>(
        ab[1], w + woff[2], b[2], ab[0], nullptr, MID, MID);
    mma_gemm<true, false><<<grid_mid, blk, SMEM_TOTAL>>>(
        ab[0], w + woff[3], b[3], ab[1], nullptr, MID, MID);
    mma_gemm<true, false><<<grid_mid, blk, SMEM_TOTAL>>>(
        ab[1], w + woff[4], b[4], ab[0], nullptr, MID, MID);
    // L5: [8192,4096] @ Wt5^T -> [8192,512] fp32, no relu
    mma_gemm<false, true><<<grid_last, blk, SMEM_TOTAL>>>(
        ab[0], w + woff[5], b[5], nullptr, m, HALF, MID);

    int tail = out_size - BATCH * IN_OUT_DIM;
    if (tail < 0) tail = 0;
    finalize_kernel<<<(n_pairs + 255) / 256, 256>>>(x, m, ldj, out, tail);
}

// round 14
// speedup vs baseline: 1.0596x; 1.0209x over previous
#include <cuda_runtime.h>
#include <cuda_fp16.h>
#include <cstdint>

#define BATCH 8192
#define IN_OUT_DIM 1024
#define HALF 512
#define MID 4096

// Weight element offsets in the packed transposed-weight buffer ([N,K] fp16).
#define WO0 0                       // Wt0 [4096,512]
#define WO1 (WO0 + 4096*512)        // Wt1 [4096,4096]
#define WO2 (WO1 + 4096*4096)
#define WO3 (WO2 + 4096*4096)
#define WO4 (WO3 + 4096*4096)
#define WO5 (WO4 + 4096*4096)       // Wt5 [512,4096]
#define WTOT (WO5 + 512*4096)

// ---------------------------------------------------------------------------
// Scratch (allocation-free rule -> device globals)
// ---------------------------------------------------------------------------
__device__ __align__(1024) unsigned short g_odd[BATCH * HALF];        // fp16
__device__ __align__(1024) unsigned short g_a[2][BATCH * MID];        // fp16
__device__ __align__(1024) unsigned short g_w[WTOT];                  // fp16

// ---------------------------------------------------------------------------
// PTX helpers (sm_80-level: cp.async, ldmatrix, mma.sync)
// ---------------------------------------------------------------------------
__device__ __forceinline__ uint32_t smem_to_u32(const void* p) {
    uint32_t a;
    asm("{ .reg .u64 t; cvta.to.shared.u64 t, %1; cvt.u32.u64 %0, t; }" : "=r"(a) : "l"(p));
    return a;
}

__device__ __forceinline__ void cp_async16(uint32_t dst, const void* src) {
    asm volatile("cp.async.cg.shared.global [%0], [%1], 16;" :: "r"(dst), "l"(src));
}
__device__ __forceinline__ void cp_commit() {
    asm volatile("cp.async.commit_group;" ::: "memory");
}
template <int N>
__device__ __forceinline__ void cp_wait() {
    asm volatile("cp.async.wait_group %0;" :: "n"(N) : "memory");
}

#define LDMATRIX_X4(r0, r1, r2, r3, addr) \
    asm volatile("ldmatrix.sync.aligned.m8n8.x4.shared.b16 {%0,%1,%2,%3}, [%4];" \
                 : "=r"(r0), "=r"(r1), "=r"(r2), "=r"(r3) : "r"(addr))

// D(f32) += A(f16,row) * B(f16,col);  C/D 4 regs, A 4 regs, B 2 regs
__device__ __forceinline__ void mma_f16(float* c, const uint32_t* a, const uint32_t* b) {
    asm volatile(
        "mma.sync.aligned.m16n8k16.row.col.f32.f16.f16.f32 "
        "{%0,%1,%2,%3}, {%4,%5,%6,%7}, {%8,%9}, {%0,%1,%2,%3};"
        : "+f"(c[0]), "+f"(c[1]), "+f"(c[2]), "+f"(c[3])
        : "r"(a[0]), "r"(a[1]), "r"(a[2]), "r"(a[3]), "r"(b[0]), "r"(b[1]));
}

// ---------------------------------------------------------------------------
// Prep kernels
// ---------------------------------------------------------------------------
__global__ void extract_odd_f16(const float* __restrict__ x,
                                const float* __restrict__ ldj,
                                float* __restrict__ out,
                                unsigned short* __restrict__ o,
                                int tail) {
    int i = blockIdx.x * blockDim.x + threadIdx.x;
    if (i < BATCH * HALF) {
        float2 v = reinterpret_cast<const float2*>(x)[i];
        o[i] = __half_as_ushort(__float2half_rn(v.y));
    }
    if (i < tail) {
        out[BATCH * IN_OUT_DIM + i] = ldj[i];
    }
}

// W [K,N] fp32 (row-major) -> Wt [N,K] fp16.  64x64 tile, 256 threads.
__global__ void transpose_f16(const float* __restrict__ W,
                              unsigned short* __restrict__ T,
                              int K, int N) {
    __shared__ float t[64][65];
    const int n0 = blockIdx.x * 64, k0 = blockIdx.y * 64;
    const int tid = threadIdx.x;

    #pragma unroll
    for (int j = 0; j < 4; j++) {
        int idx = tid + 256 * j;
        int r = idx >> 4;            // k-row 0..63
        int c4 = (idx & 15) * 4;     // n-col group
        float4 v = *reinterpret_cast<const float4*>(
            W + (size_t)(k0 + r) * N + n0 + c4);
        t[r][c4 + 0] = v.x;
        t[r][c4 + 1] = v.y;
        t[r][c4 + 2] = v.z;
        t[r][c4 + 3] = v.w;
    }
    __syncthreads();

    const int lane = tid & 31;
    const int w = tid >> 5;
    const int chunk = lane & 7;          // k-chunk 0..7 (8 fp16 each)
    #pragma unroll
    for (int rep = 0; rep < 2; rep++) {
        int nloc = w * 8 + rep * 4 + (lane >> 3);  // n-row 0..63
        unsigned short h[8];
        #pragma unroll
        for (int j = 0; j < 8; j++)
            h[j] = __half_as_ushort(__float2half_rn(t[chunk * 8 + j][nloc]));
        uint4 o;
        o.x = (uint32_t)h[0] | ((uint32_t)h[1] << 16);
        o.y = (uint32_t)h[2] | ((uint32_t)h[3] << 16);
        o.z = (uint32_t)h[4] | ((uint32_t)h[5] << 16);
        o.w = (uint32_t)h[6] | ((uint32_t)h[7] << 16);
        *reinterpret_cast<uint4*>(T + (size_t)(n0 + nloc) * K + k0 + chunk * 8) = o;
    }
}

// ---------------------------------------------------------------------------
// fp16 HMMA GEMM: C[M,N] = A[M,K] @ Wt[N,K]^T + bias, fp32 accum.
// BM=128, BN=128, BK=64; 256 threads (8 warps, 2x4 of 64x32 warp tiles);
// 3-stage cp.async pipeline, ONE __syncthreads per iteration; occupancy 2;
// fragment double-buffering across kk (LDSM for kk+1 overlap MMAs of kk).
// FINAL=true fuses the coupling epilogue: writes interleaved fp32 output
// out[r, 2c] = x[r, 2c] + (acc + bias), out[r, 2c+1] = x[r, 2c+1].
// ---------------------------------------------------------------------------
#define BM 128
#define BN 128
#define BK 64
#define NTHREADS 256
#define NSTAGE 3
#define A_OFF 0
#define B_OFF 16384
#define STAGE_SZ 32768
#define SMEM_TOTAL (NSTAGE * STAGE_SZ + 1024)

// 128B rows (64 fp16): sw = (row*128 + col) ^ ((row&7)<<4)
__device__ __forceinline__ uint32_t swz(int row, int bytecol) {
    return (uint32_t)(row * 128 + bytecol) ^ (uint32_t)((row & 7) << 4);
}

__device__ __forceinline__ void load_stage(
    uint32_t stage_base,
    const unsigned short* A, const unsigned short* B,
    int lda, int tid) {
    #pragma unroll
    for (int j = 0; j < 4; j++) {
        int c = tid + NTHREADS * j;
        int row = c >> 3;
        int col = (c & 7) * 16;
        uint32_t sw = swz(row, col);
        cp_async16(stage_base + A_OFF + sw, (const char*)(A + (size_t)row * lda) + col);
        cp_async16(stage_base + B_OFF + sw, (const char*)(B + (size_t)row * lda) + col);
    }
}

template <bool RELU, bool FINAL>
__global__ void __launch_bounds__(NTHREADS, 2)
mma_gemm(const unsigned short* __restrict__ A,
         const unsigned short* __restrict__ B,
         const float* __restrict__ bias,
         unsigned short* __restrict__ C,     // fp16 activation out
         const float* __restrict__ X,        // original x (FINAL)
         float* __restrict__ Ofull,          // fp32 interleaved out (FINAL)
         int N, int K) {
    extern __shared__ char dyn_smem[];
    const uint32_t sbase = (smem_to_u32(dyn_smem) + 1023u) & ~1023u;

    const int tid = threadIdx.x;
    const int wid = tid >> 5;
    const int lane = tid & 31;
    const int warp_m = wid & 1;   // 2 warps over M (64 rows each)
    const int warp_n = wid >> 1;  // 4 warps over N (32 cols each)

    const int m0 = blockIdx.y * BM;
    const int n0 = blockIdx.x * BN;
    const unsigned short* At = A + (size_t)m0 * K;
    const unsigned short* Bt = B + (size_t)n0 * K;

    const int niter = K / BK;

    #pragma unroll
    for (int s = 0; s < NSTAGE - 1; s++) {
        load_stage(sbase + s * STAGE_SZ, At + s * BK, Bt + s * BK, K, tid);
        cp_commit();
    }

    float acc[4][4][4];
    #pragma unroll
    for (int mi = 0; mi < 4; mi++)
        #pragma unroll
        for (int nj = 0; nj < 4; nj++)
            #pragma unroll
            for (int q = 0; q < 4; q++) acc[mi][nj][q] = 0.0f;

    const int a_row_base = warp_m * 64 + (lane & 15);                // + mi*16
    const int a_col_sel = ((lane >> 4) & 1) * 16;                    // + kk*32
    const int b_row_base = warp_n * 32 + (lane & 7) + ((lane >> 4) & 1) * 8;  // + njp*16
    const int b_col_sel = ((lane >> 3) & 1) * 16;                    // + kk*32

    // Fragment double buffers: [buf][...]
    uint32_t a_f[2][4][4];
    uint32_t b_f[2][2][2][2];   // [buf][njp][njq][reg]

#define LOAD_FRAGS(kk, buf, so)                                              \
    {                                                                        \
        const int acol = a_col_sel + (kk) * 32;                              \
        const int bcol = b_col_sel + (kk) * 32;                              \
        _Pragma("unroll")                                                    \
        for (int mi = 0; mi < 4; mi++) {                                     \
            const int row = a_row_base + mi * 16;                            \
            const uint32_t sw = swz(row, acol);                              \
            LDMATRIX_X4(a_f[buf][mi][0], a_f[buf][mi][1],                    \
                        a_f[buf][mi][2], a_f[buf][mi][3], (so) + A_OFF + sw);\
        }                                                                    \
        _Pragma("unroll")                                                    \
        for (int njp = 0; njp < 2; njp++) {                                  \
            const int row = b_row_base + njp * 16;                           \
            const uint32_t sw = swz(row, bcol);                              \
            LDMATRIX_X4(b_f[buf][njp][0][0], b_f[buf][njp][0][1],            \
                        b_f[buf][njp][1][0], b_f[buf][njp][1][1],            \
                        (so) + B_OFF + sw);                                  \
        }                                                                    \
    }

    for (int i = 0; i < niter; i++) {
        cp_wait<NSTAGE - 2>();   // stage i resident
        __syncthreads();         // all warps past compute(i-1); its slot is free

        if (i + NSTAGE - 1 < niter) {
            int kb = (i + NSTAGE - 1) * BK;
            load_stage(sbase + ((i + NSTAGE - 1) % NSTAGE) * STAGE_SZ,
                       At + kb, Bt + kb, K, tid);
        }
        cp_commit();  // uniform group accounting (possibly empty)

        const uint32_t so = sbase + (i % NSTAGE) * STAGE_SZ;

        LOAD_FRAGS(0, 0, so);
        #pragma unroll
        for (int kk = 0; kk < 4; kk++) {
            const int cur = kk & 1;
            if (kk < 3) LOAD_FRAGS(kk + 1, cur ^ 1, so);
            #pragma unroll
            for (int mi = 0; mi < 4; mi++) {
                #pragma unroll
                for (int njp = 0; njp < 2; njp++) {
                    #pragma unroll
                    for (int njq = 0; njq < 2; njq++) {
                        mma_f16(acc[mi][2 * njp + njq], a_f[cur][mi],
                                b_f[cur][njp][njq]);
                    }
                }
            }
        }
    }
#undef LOAD_FRAGS

    // Epilogue: c0,c1 -> row g, cols p,p+1; c2,c3 -> row g+8
    const int g = lane >> 2;
    const int p = (lane & 3) * 2;
    #pragma unroll
    for (int mi = 0; mi < 4; mi++) {
        #pragma unroll
        for (int nj = 0; nj < 4; nj++) {
            const int col = n0 + warp_n * 32 + nj * 8 + p;
            const float bx = bias[col];
            const float by = bias[col + 1];
            #pragma unroll
            for (int half = 0; half < 2; half++) {
                const int r = m0 + warp_m * 64 + mi * 16 + g + half * 8;
                float v0 = acc[mi][nj][2 * half + 0] + bx;
                float v1 = acc[mi][nj][2 * half + 1] + by;
                if (RELU) {
                    v0 = fmaxf(v0, 0.0f);
                    v1 = fmaxf(v1, 0.0f);
                }
                if (FINAL) {
                    // out[r,2col]=x[r,2col]+v0; out[r,2col+1]=x[r,2col+1];
                    // out[r,2col+2]=x[r,2col+2]+v1; out[r,2col+3]=x[r,2col+3]
                    const size_t base = (size_t)r * IN_OUT_DIM + 2 * col;
                    float4 xv = *reinterpret_cast<const float4*>(X + base);
                    float4 o;
                    o.x = xv.x + v0;
                    o.y = xv.y;
                    o.z = xv.z + v1;
                    o.w = xv.w;
                    *reinterpret_cast<float4*>(Ofull + base) = o;
                } else {
                    uint32_t h0 = (uint32_t)__half_as_ushort(__float2half_rn(v0));
                    uint32_t h1 = (uint32_t)__half_as_ushort(__float2half_rn(v1));
                    *reinterpret_cast<uint32_t*>(C + (size_t)r * N + col) =
                        (h1 << 16) | h0;
                }
            }
        }
    }
}

// ---------------------------------------------------------------------------
extern "C" void kernel_launch(void* const* d_in, const int* in_sizes, int n_in,
                              void* d_out, int out_size) {
    const float* x   = (const float*)d_in[0];
    const float* ldj = (const float*)d_in[1];
    const float* W[6] = {(const float*)d_in[2], (const float*)d_in[4],
                         (const float*)d_in[6], (const float*)d_in[8],
                         (const float*)d_in[10], (const float*)d_in[12]};
    const float* b[6] = {(const float*)d_in[3], (const float*)d_in[5],
                         (const float*)d_in[7], (const float*)d_in[9],
                         (const float*)d_in[11], (const float*)d_in[13]};
    float* out = (float*)d_out;

    unsigned short *odd, *a, *w;
    cudaGetSymbolAddress((void**)&odd, g_odd);
    cudaGetSymbolAddress((void**)&a, g_a);
    cudaGetSymbolAddress((void**)&w, g_w);

    unsigned short* ab[2] = {a, a + (size_t)BATCH * MID};
    const size_t woff[6] = {WO0, WO1, WO2, WO3, WO4, WO5};

    // --- prep ---
    const int n_pairs = BATCH * HALF;
    int tail = out_size - BATCH * IN_OUT_DIM;
    if (tail < 0) tail = 0;
    extract_odd_f16<<<(n_pairs + 255) / 256, 256>>>(x, ldj, out, odd, tail);

    // W0 [512,4096] -> Wt0 [4096,512]
    transpose_f16<<<dim3(4096 / 64, 512 / 64), 256>>>(W[0], w + woff[0], 512, 4096);
    for (int i = 1; i <= 4; i++)
        transpose_f16<<<dim3(4096 / 64, 4096 / 64), 256>>>(W[i], w + woff[i], 4096, 4096);
    // W5 [4096,512] -> Wt5 [512,4096]
    transpose_f16<<<dim3(512 / 64, 4096 / 64), 256>>>(W[5], w + woff[5], 4096, 512);

    // --- GEMM chain ---
    cudaFuncSetAttribute(mma_gemm<true, false>,
                         cudaFuncAttributeMaxDynamicSharedMemorySize, SMEM_TOTAL);
    cudaFuncSetAttribute(mma_gemm<false, true>,
                         cudaFuncAttributeMaxDynamicSharedMemorySize, SMEM_TOTAL);

    dim3 blk(NTHREADS);
    dim3 grid_mid(MID / BN, BATCH / BM);   // (32, 64)
    dim3 grid_last(HALF / BN, BATCH / BM); // (4, 64)

    // L0: [8192,512] @ Wt0^T -> [8192,4096], relu
    mma_gemm<true, false><<<grid_mid, blk, SMEM_TOTAL>>>(
        odd, w + woff[0], b[0], ab[0], nullptr, nullptr, MID, HALF);
    // L1..L4: [8192,4096] @ Wt^T -> [8192,4096], relu (ping-pong)
    mma_gemm<true, false><<<grid_mid, blk, SMEM_TOTAL>>>(
        ab[0], w + woff[1], b[1], ab[1], nullptr, nullptr, MID, MID);
    mma_gemm<true, false><<<grid_mid, blk, SMEM_TOTAL>>>(
        ab[1], w + woff[2], b[2], ab[0], nullptr, nullptr, MID, MID);
    mma_gemm<true, false><<<grid_mid, blk, SMEM_TOTAL>>>(
        ab[0], w + woff[3], b[3], ab[1], nullptr, nullptr, MID, MID);
    mma_gemm<true, false><<<grid_mid, blk, SMEM_TOTAL>>>(
        ab[1], w + woff[4], b[4], ab[0], nullptr, nullptr, MID, MID);
    // L5: [8192,4096] @ Wt5^T + coupling epilogue -> out (fp32 interleaved)
    mma_gemm<false, true><<<grid_last, blk, SMEM_TOTAL>>>(
        ab[0], w + woff[5], b[5], nullptr, x, out, HALF, MID);
}